// round 1
// baseline (speedup 1.0000x reference)
#include <cuda_runtime.h>

// LIF neuron scan.
// Inputs : d_in[0] = input_current  f32 [B=32, T=1000, N=1024]
//          d_in[1] = v_init         f32 [B=32, N=1024]
// Output : d_out = [2, B, T, N] f32  (spikes block, then voltages block)
//
// Recurrence (must match JAX reference bit-for-bit where possible):
//   v = v + (i - v) / 10.0     (true IEEE division in the reference)
//   s = (v >= 1.0) ? 1 : 0
//   v = s ? 0 : v
//
// Division by the constant 10 is done with the Markstein FMA sequence,
// which produces the correctly-rounded (RN) quotient identical to div.rn.f32
// for all normal inputs, in 4 ops instead of the ~10-op div expansion.

#define LIF_B 32
#define LIF_T 1000
#define LIF_N 1024
#define LIF_U 8   // time-unroll depth (MLP per thread); 1000 % 8 == 0

static __global__ __launch_bounds__(128)
void lif_scan_kernel(const float* __restrict__ in,
                     const float* __restrict__ v0,
                     float* __restrict__ out)
{
    const int gid = blockIdx.x * 128 + threadIdx.x;   // 0 .. B*N-1
    const int b = gid >> 10;            // gid / N
    const int n = gid & (LIF_N - 1);    // gid % N

    const long long base = (long long)b * (LIF_T * LIF_N) + n;
    const long long BTN  = (long long)LIF_B * LIF_T * LIF_N;

    const float* ip = in  + base;
    float*       sp = out + base;          // spikes block
    float*       vp = out + BTN + base;    // voltages block

    float v = v0[gid];                     // v_init[b, n]

    const float r = 0.1f;                  // RN(1/10)

    #pragma unroll 1
    for (int t0 = 0; t0 < LIF_T; t0 += LIF_U) {
        // Front-batched loads: U independent LDGs in flight per thread.
        float cur[LIF_U];
        #pragma unroll
        for (int u = 0; u < LIF_U; ++u) {
            cur[u] = __ldcs(ip + (long long)(t0 + u) * LIF_N);
        }

        #pragma unroll
        for (int u = 0; u < LIF_U; ++u) {
            // x = (-(v - 0) + i)  ==  i - v   (IEEE-identical)
            float x  = cur[u] - v;
            // Correctly-rounded x / 10.0f via Markstein FMA sequence:
            float q0 = x * r;
            float e  = fmaf(-10.0f, q0, x);
            float q  = fmaf(e, r, q0);
            v = v + q;

            float s = (v >= 1.0f) ? 1.0f : 0.0f;
            v       = (v >= 1.0f) ? 0.0f : v;

            __stcs(sp + (long long)(t0 + u) * LIF_N, s);
            __stcs(vp + (long long)(t0 + u) * LIF_N, v);
        }
    }
}

extern "C" void kernel_launch(void* const* d_in, const int* in_sizes, int n_in,
                              void* d_out, int out_size)
{
    const float* in = (const float*)d_in[0];   // [B, T, N]
    const float* v0 = (const float*)d_in[1];   // [B, N]
    float* out = (float*)d_out;                // [2, B, T, N]

    (void)in_sizes; (void)n_in; (void)out_size;

    const int total  = LIF_B * LIF_N;          // 32768 threads
    const int block  = 128;
    const int grid   = total / block;          // 256 CTAs

    lif_scan_kernel<<<grid, block>>>(in, v0, out);
}

// round 2
// speedup vs baseline: 1.6345x; 1.6345x over previous
#include <cuda_runtime.h>

// LIF neuron scan — latency-optimized (deep MLP + double-buffered loads).
// Inputs : d_in[0] = input_current  f32 [B=32, T=1000, N=1024]
//          d_in[1] = v_init         f32 [B=32, N=1024]
// Output : d_out = [2, B, T, N] f32  (spikes block, then voltages block)
//
// Recurrence:
//   v = v + (i - v) / 10.0     (correctly-rounded div via Markstein FMA seq)
//   s = (v >= 1.0) ? 1 : 0
//   v = s ? 0 : v

#define LIF_B 32
#define LIF_T 1000
#define LIF_N 1024
#define LIF_U 20   // chunk depth; 1000 % (2*20) == 0 -> 25 ping-pong pairs

static __device__ __forceinline__ float lif_step(float v, float i,
                                                 float& s_out)
{
    float x  = i - v;                 // (-(v-0) + i)
    float q0 = x * 0.1f;              // Markstein: correctly-rounded x/10
    float e  = fmaf(-10.0f, q0, x);
    float q  = fmaf(e, 0.1f, q0);
    v = v + q;
    s_out = (v >= 1.0f) ? 1.0f : 0.0f;
    return (v >= 1.0f) ? 0.0f : v;
}

static __global__ __launch_bounds__(128)
void lif_scan_kernel(const float* __restrict__ in,
                     const float* __restrict__ v0,
                     float* __restrict__ out)
{
    const int gid = blockIdx.x * 128 + threadIdx.x;   // 0 .. B*N-1
    const int b = gid >> 10;
    const int n = gid & (LIF_N - 1);

    const long long base = (long long)b * (LIF_T * LIF_N) + n;
    const long long BTN  = (long long)LIF_B * LIF_T * LIF_N;

    const float* ip = in  + base;
    float*       sp = out + base;          // spikes block
    float*       vp = out + BTN + base;    // voltages block

    float v = v0[gid];

    float bufA[LIF_U];
    float bufB[LIF_U];

    // Prologue: fill buffer A with chunk 0.
    #pragma unroll
    for (int u = 0; u < LIF_U; ++u)
        bufA[u] = __ldcs(ip + (long long)u * LIF_N);

    #pragma unroll 1
    for (int t0 = 0; t0 < LIF_T; t0 += 2 * LIF_U) {
        // ---- prefetch chunk (t0 + U) into B, then consume A (chunk t0) ----
        #pragma unroll
        for (int u = 0; u < LIF_U; ++u)
            bufB[u] = __ldcs(ip + (long long)(t0 + LIF_U + u) * LIF_N);

        #pragma unroll
        for (int u = 0; u < LIF_U; ++u) {
            float s;
            v = lif_step(v, bufA[u], s);
            __stcs(sp + (long long)(t0 + u) * LIF_N, s);
            __stcs(vp + (long long)(t0 + u) * LIF_N, v);
        }

        // ---- prefetch chunk (t0 + 2U) into A, then consume B (t0 + U) ----
        if (t0 + 2 * LIF_U < LIF_T) {
            #pragma unroll
            for (int u = 0; u < LIF_U; ++u)
                bufA[u] = __ldcs(ip + (long long)(t0 + 2 * LIF_U + u) * LIF_N);
        }

        #pragma unroll
        for (int u = 0; u < LIF_U; ++u) {
            float s;
            v = lif_step(v, bufB[u], s);
            __stcs(sp + (long long)(t0 + LIF_U + u) * LIF_N, s);
            __stcs(vp + (long long)(t0 + LIF_U + u) * LIF_N, v);
        }
    }
}

extern "C" void kernel_launch(void* const* d_in, const int* in_sizes, int n_in,
                              void* d_out, int out_size)
{
    const float* in = (const float*)d_in[0];   // [B, T, N]
    const float* v0 = (const float*)d_in[1];   // [B, N]
    float* out = (float*)d_out;                // [2, B, T, N]

    (void)in_sizes; (void)n_in; (void)out_size;

    const int total = LIF_B * LIF_N;           // 32768 threads
    const int block = 128;
    const int grid  = total / block;           // 256 CTAs

    lif_scan_kernel<<<grid, block>>>(in, v0, out);
}

// round 3
// speedup vs baseline: 1.8229x; 1.1152x over previous
#include <cuda_runtime.h>
#include <cstdint>

// LIF neuron scan — bulk-async (UBLKCP) SMEM input pipeline, direct streamed stores.
// Inputs : d_in[0] = input_current  f32 [B=32, T=1000, N=1024]
//          d_in[1] = v_init         f32 [B=32, N=1024]
// Output : d_out = [2, B, T, N] f32  (spikes block, then voltages block)
//
// Recurrence:
//   v = v + (i - v) / 10.0     (correctly-rounded div via Markstein FMA seq)
//   s = (v >= 1.0) ? 1 : 0
//   v = s ? 0 : v

#define LIF_B   32
#define LIF_T   1000
#define LIF_N   1024
#define TC      20                 // timesteps per chunk
#define NSTAGE  4                  // pipeline depth
#define NPC     128                // neurons per CTA
#define NTHREAD 64                 // threads per CTA (2 neurons each)
#define NCHUNK  (LIF_T / TC)       // 50
#define ROW_BYTES (NPC * 4)        // 512
#define STAGE_BYTES (TC * ROW_BYTES)  // 10240

struct __align__(1024) LifSmem {
    float tile[NSTAGE][TC][NPC];          // 40960 B
    unsigned long long mbar[NSTAGE];
};

static __device__ __forceinline__ unsigned smem_u32(const void* p) {
    return (unsigned)__cvta_generic_to_shared(p);
}

static __device__ __forceinline__ void mbar_init(unsigned mbar, unsigned count) {
    asm volatile("mbarrier.init.shared.b64 [%0], %1;" :: "r"(mbar), "r"(count) : "memory");
}

static __device__ __forceinline__ void mbar_expect_tx(unsigned mbar, unsigned bytes) {
    asm volatile("mbarrier.arrive.expect_tx.shared.b64 _, [%0], %1;"
                 :: "r"(mbar), "r"(bytes) : "memory");
}

static __device__ __forceinline__ void mbar_wait(unsigned mbar, unsigned parity) {
    asm volatile(
        "{\n\t"
        ".reg .pred P1;\n\t"
        "LAB_WAIT_%=:\n\t"
        "mbarrier.try_wait.parity.acquire.cta.shared::cta.b64 P1, [%0], %1, 0x989680;\n\t"
        "@P1 bra LAB_DONE_%=;\n\t"
        "bra LAB_WAIT_%=;\n\t"
        "LAB_DONE_%=:\n\t"
        "}"
        :: "r"(mbar), "r"(parity) : "memory");
}

static __device__ __forceinline__ void bulk_cp_g2s(unsigned dst_smem, const void* gsrc,
                                                   unsigned bytes, unsigned mbar) {
    asm volatile(
        "cp.async.bulk.shared::cta.global.mbarrier::complete_tx::bytes [%0], [%1], %2, [%3];"
        :: "r"(dst_smem), "l"(gsrc), "r"(bytes), "r"(mbar) : "memory");
}

static __device__ __forceinline__ float lif_step(float v, float i, float& s_out) {
    float x  = i - v;                  // (-(v - 0) + i)
    float q0 = x * 0.1f;               // Markstein: correctly-rounded x/10
    float e  = fmaf(-10.0f, q0, x);
    float q  = fmaf(e, 0.1f, q0);
    v = v + q;
    s_out = (v >= 1.0f) ? 1.0f : 0.0f;
    return (v >= 1.0f) ? 0.0f : v;
}

static __device__ __forceinline__ void issue_chunk(LifSmem& sm, int c, const float* gsrc) {
    const int s = c & (NSTAGE - 1);
    const unsigned mb = smem_u32(&sm.mbar[s]);
    mbar_expect_tx(mb, STAGE_BYTES);
    #pragma unroll
    for (int r = 0; r < TC; ++r) {
        const float* src = gsrc + (long long)(c * TC + r) * LIF_N;
        bulk_cp_g2s(smem_u32(&sm.tile[s][r][0]), src, ROW_BYTES, mb);
    }
}

static __global__ __launch_bounds__(NTHREAD)
void lif_scan_kernel(const float* __restrict__ in,
                     const float* __restrict__ v0,
                     float* __restrict__ out)
{
    __shared__ LifSmem sm;

    const int tid = threadIdx.x;
    const int b   = blockIdx.x >> 3;          // 32 batches
    const int n0  = (blockIdx.x & 7) * NPC;   // 8 neuron-blocks of 128

    if (tid == 0) {
        #pragma unroll
        for (int i = 0; i < NSTAGE; ++i)
            mbar_init(smem_u32(&sm.mbar[i]), 1);
        asm volatile("fence.proxy.async.shared::cta;" ::: "memory");
    }
    __syncthreads();

    const float* gsrc = in + (long long)b * (LIF_T * LIF_N) + n0;

    // Prologue: fill all pipeline stages.
    if (tid == 0) {
        #pragma unroll
        for (int c = 0; c < NSTAGE; ++c)
            issue_chunk(sm, c, gsrc);
    }

    // Per-thread state: 2 neurons.
    float2 v = *(const float2*)(v0 + (long long)b * LIF_N + n0 + 2 * tid);

    float* sp = out + (long long)b * (LIF_T * LIF_N) + n0 + 2 * tid;       // spikes
    float* vp = sp + (long long)LIF_B * LIF_T * LIF_N;                     // voltages

    #pragma unroll 1
    for (int c = 0; c < NCHUNK; ++c) {
        const int s = c & (NSTAGE - 1);
        const unsigned parity = (c >> 2) & 1;

        mbar_wait(smem_u32(&sm.mbar[s]), parity);

        #pragma unroll
        for (int r = 0; r < TC; ++r) {
            float2 cur = ((const float2*)&sm.tile[s][r][0])[tid];
            float s0, s1;
            v.x = lif_step(v.x, cur.x, s0);
            v.y = lif_step(v.y, cur.y, s1);
            const long long off = (long long)(c * TC + r) * LIF_N;
            __stcs((float2*)(sp + off), make_float2(s0, s1));
            __stcs((float2*)(vp + off), v);
        }

        __syncthreads();   // all threads done reading stage s

        if (tid == 0 && c + NSTAGE < NCHUNK)
            issue_chunk(sm, c + NSTAGE, gsrc);
    }
}

extern "C" void kernel_launch(void* const* d_in, const int* in_sizes, int n_in,
                              void* d_out, int out_size)
{
    const float* in = (const float*)d_in[0];   // [B, T, N]
    const float* v0 = (const float*)d_in[1];   // [B, N]
    float* out = (float*)d_out;                // [2, B, T, N]

    (void)in_sizes; (void)n_in; (void)out_size;

    const int grid = LIF_B * (LIF_N / NPC);    // 256 CTAs
    lif_scan_kernel<<<grid, NTHREAD>>>(in, v0, out);
}